// round 1
// baseline (speedup 1.0000x reference)
#include <cuda_runtime.h>
#include <math.h>

#define N_VAR 50000
#define N_CLA 100000
#define NM    150000
#define DD    64
#define NC    1000
#define VC    64
#define KCL   128
#define NN    192      // nodes per cluster = VC + KCL
#define NE    8000
#define NSH   8
#define NITER 3
#define NEG   0.2f
#define GAMMA 1.0f
#define INVSCALE 0.125f   // 1/sqrt(64)

// ---------------- scratch (static device globals; no runtime alloc) ----------
__device__ float g_x  [NM * DD];   // [vars | clauses]
__device__ float g_Q  [NM * DD];
__device__ float g_K  [NM * DD];
__device__ float g_V  [NM * DD];
__device__ float g_acc[NM * DD];
__device__ float g_cnt[NM];
__device__ float g_Q2 [NC * DD];
__device__ float g_K2 [NC * DD];
__device__ float g_V2 [NC * DD];
__device__ float g_pool[2 * DD];

// ---------------- init: pack x_var / x_clause into g_x -----------------------
__global__ void k_init(const float* __restrict__ xv, const float* __restrict__ xc) {
    int stride = gridDim.x * blockDim.x;
    for (int i = blockIdx.x * blockDim.x + threadIdx.x; i < NM * DD; i += stride)
        g_x[i] = (i < N_VAR * DD) ? xv[i] : xc[i - N_VAR * DD];
}

// ---------------- zero accumulators ------------------------------------------
__global__ void k_zero() {
    int stride = gridDim.x * blockDim.x;
    int t = blockIdx.x * blockDim.x + threadIdx.x;
    for (int i = t; i < NM * DD; i += stride) g_acc[i] = 0.f;
    for (int i = t; i < NM; i += stride)      g_cnt[i] = 0.f;
}

__global__ void k_poolzero() {
    if (threadIdx.x < 2 * DD) g_pool[threadIdx.x] = 0.f;
}

// ---------------- Q/K/V projection: y = x @ W^T ------------------------------
// 64 rows per block, warp-per-row (8 rows per warp). Weights transposed in smem.
__global__ void k_proj(const float* __restrict__ WQ,
                       const float* __restrict__ WK,
                       const float* __restrict__ WV) {
    extern __shared__ float sm[];
    float* Wt = sm;                 // 3 * 64*65
    float* xs = sm + 3 * 64 * 65;   // 8 * 64
    int tid = threadIdx.x;
    for (int i = tid; i < 64 * 64; i += 256) {
        int d = i >> 6, k = i & 63;             // W[d][k]
        Wt[0 * 64 * 65 + k * 65 + d] = WQ[i];
        Wt[1 * 64 * 65 + k * 65 + d] = WK[i];
        Wt[2 * 64 * 65 + k * 65 + d] = WV[i];
    }
    __syncthreads();
    int warp = tid >> 5, lane = tid & 31;
    float* xw = xs + warp * 64;
    for (int rr = 0; rr < 8; rr++) {
        int r = blockIdx.x * 64 + rr * 8 + warp;
        if (r >= NM) continue;
        const float* xr = g_x + (size_t)r * DD;
        xw[lane]      = xr[lane];
        xw[lane + 32] = xr[lane + 32];
        __syncwarp();
        float q0 = 0, q1 = 0, kk0 = 0, kk1 = 0, v0 = 0, v1 = 0;
        #pragma unroll 16
        for (int k = 0; k < 64; k++) {
            float xvv = xw[k];
            q0  = fmaf(xvv, Wt[k * 65 + lane],                    q0);
            q1  = fmaf(xvv, Wt[k * 65 + lane + 32],               q1);
            kk0 = fmaf(xvv, Wt[64 * 65 + k * 65 + lane],          kk0);
            kk1 = fmaf(xvv, Wt[64 * 65 + k * 65 + lane + 32],     kk1);
            v0  = fmaf(xvv, Wt[2 * 64 * 65 + k * 65 + lane],      v0);
            v1  = fmaf(xvv, Wt[2 * 64 * 65 + k * 65 + lane + 32], v1);
        }
        size_t o = (size_t)r * DD;
        g_Q[o + lane] = q0; g_Q[o + lane + 32] = q1;
        g_K[o + lane] = kk0; g_K[o + lane + 32] = kk1;
        g_V[o + lane] = v0; g_V[o + lane + 32] = v1;
        __syncwarp();
    }
}

// ---------------- intra-cluster attention (GAT1 core) ------------------------
// One block per cluster. K,V tiles in SMEM (stride 65 -> conflict free).
// Warp per query row; lane-per-key for scores, lane-per-dim for output.
__global__ void k_attn(const int* __restrict__ cvar, const int* __restrict__ ccla,
                       const float* __restrict__ sat, const float* __restrict__ hw) {
    extern __shared__ float sm[];
    float* Ksh = sm;                    // NN*65
    float* Vsh = Ksh + NN * 65;         // NN*65
    float* wsh = Vsh + NN * 65;         // 8*NN
    float* qsh = wsh + 8 * NN;          // 8*64
    float* bsh = qsh + 8 * 64;          // NN
    int*   nsh = (int*)(bsh + NN);      // NN

    int c = blockIdx.x, tid = threadIdx.x;
    if (tid < NN) {
        int g; float b;
        if (tid < VC) { g = cvar[c * VC + tid]; b = 0.f; }
        else { int cl = ccla[c * KCL + (tid - VC)]; g = N_VAR + cl; b = GAMMA * sat[cl]; }
        nsh[tid] = g; bsh[tid] = b;
    }
    __syncthreads();
    for (int i = tid; i < NN * DD; i += 256) {
        int j = i >> 6, d = i & 63;
        size_t o = (size_t)nsh[j] * DD + d;
        Ksh[j * 65 + d] = g_K[o];
        Vsh[j * 65 + d] = g_V[o];
    }
    float hwm = 0.25f * (hw[0] + hw[1] + hw[2] + hw[3]);
    __syncthreads();

    int warp = tid >> 5, lane = tid & 31;
    float* qw = qsh + warp * 64;
    float* ww = wsh + warp * NN;
    for (int i = warp; i < NN; i += 8) {
        int g = nsh[i];
        size_t qo = (size_t)g * DD;
        qw[lane]      = g_Q[qo + lane];
        qw[lane + 32] = g_Q[qo + lane + 32];
        __syncwarp();

        float acc[6] = {0.f, 0.f, 0.f, 0.f, 0.f, 0.f};
        #pragma unroll 8
        for (int d = 0; d < 64; d++) {
            float q = qw[d];
            #pragma unroll
            for (int jj = 0; jj < 6; jj++)
                acc[jj] = fmaf(q, Ksh[(jj * 32 + lane) * 65 + d], acc[jj]);
        }
        float m = -1e30f;
        #pragma unroll
        for (int jj = 0; jj < 6; jj++) {
            float s = acc[jj] * INVSCALE + bsh[jj * 32 + lane];
            s = (s >= 0.f) ? s : NEG * s;
            acc[jj] = s;
            m = fmaxf(m, s);
        }
        #pragma unroll
        for (int o = 16; o > 0; o >>= 1) m = fmaxf(m, __shfl_xor_sync(0xffffffffu, m, o));
        float ssum = 0.f;
        #pragma unroll
        for (int jj = 0; jj < 6; jj++) { acc[jj] = __expf(acc[jj] - m); ssum += acc[jj]; }
        #pragma unroll
        for (int o = 16; o > 0; o >>= 1) ssum += __shfl_xor_sync(0xffffffffu, ssum, o);
        float inv = 1.f / ssum;
        #pragma unroll
        for (int jj = 0; jj < 6; jj++) ww[jj * 32 + lane] = acc[jj] * inv;
        __syncwarp();

        float o0 = 0.f, o1 = 0.f;
        #pragma unroll 8
        for (int j = 0; j < NN; j++) {
            float w = ww[j];
            o0 = fmaf(w, Vsh[j * 65 + lane],      o0);
            o1 = fmaf(w, Vsh[j * 65 + lane + 32], o1);
        }
        atomicAdd(&g_acc[(size_t)g * DD + lane],      o0 * hwm);
        atomicAdd(&g_acc[(size_t)g * DD + lane + 32], o1 * hwm);
        if (lane == 0) atomicAdd(&g_cnt[g], 1.f);
        __syncwarp();
    }
}

// ---------------- finalize: (acc/cnt) @ Wo^T + bo, residual add --------------
__global__ void k_fin(const float* __restrict__ Wo, const float* __restrict__ bo) {
    extern __shared__ float sm[];
    float* Wt = sm;            // 64*65
    float* xs = Wt + 64 * 65;  // 8*64
    int tid = threadIdx.x;
    for (int i = tid; i < 64 * 64; i += 256) {
        int d = i >> 6, k = i & 63;
        Wt[k * 65 + d] = Wo[i];
    }
    __syncthreads();
    int warp = tid >> 5, lane = tid & 31;
    float* xw = xs + warp * 64;
    for (int rr = 0; rr < 8; rr++) {
        int r = blockIdx.x * 64 + rr * 8 + warp;
        if (r >= NM) continue;
        float inv = 1.f / fmaxf(g_cnt[r], 1.f);
        size_t o = (size_t)r * DD;
        xw[lane]      = g_acc[o + lane] * inv;
        xw[lane + 32] = g_acc[o + lane + 32] * inv;
        __syncwarp();
        float y0 = bo[lane], y1 = bo[lane + 32];
        #pragma unroll 16
        for (int k = 0; k < 64; k++) {
            float a = xw[k];
            y0 = fmaf(a, Wt[k * 65 + lane],      y0);
            y1 = fmaf(a, Wt[k * 65 + lane + 32], y1);
        }
        g_x[o + lane]      += y0;
        g_x[o + lane + 32] += y1;
        __syncwarp();
    }
}

// ---------------- cluster features + Q2/K2/V2 projection ---------------------
__global__ void k_cf(const int* __restrict__ cvar,
                     const float* __restrict__ WQ2, const float* __restrict__ WK2,
                     const float* __restrict__ WV2) {
    __shared__ float cf[64];
    __shared__ int ids[64];
    int c = blockIdx.x, d = threadIdx.x;
    ids[d] = cvar[c * VC + d];
    __syncthreads();
    float s = 0.f;
    #pragma unroll 8
    for (int v = 0; v < VC; v++) s += g_x[(size_t)ids[v] * DD + d];
    cf[d] = s * (1.f / 64.f);
    __syncthreads();
    float q = 0.f, k = 0.f, v = 0.f;
    #pragma unroll 8
    for (int j = 0; j < 64; j++) {
        float x = cf[j];
        q = fmaf(x, WQ2[d * 64 + j], q);
        k = fmaf(x, WK2[d * 64 + j], k);
        v = fmaf(x, WV2[d * 64 + j], v);
    }
    g_Q2[c * 64 + d] = q; g_K2[c * 64 + d] = k; g_V2[c * 64 + d] = v;
}

// ---------------- inter-cluster edge scatter (GAT2) --------------------------
__global__ void k_edge(const int* __restrict__ ei, const int* __restrict__ shv,
                       const float* __restrict__ hw) {
    int tid = threadIdx.x;
    int warp = tid >> 5, lane = tid & 31;
    int e = blockIdx.x * 8 + warp;
    if (e >= NE) return;
    int c1 = ei[e], c2 = ei[NE + e];
    float p = g_Q2[c1 * 64 + lane] * g_K2[c2 * 64 + lane]
            + g_Q2[c1 * 64 + lane + 32] * g_K2[c2 * 64 + lane + 32];
    #pragma unroll
    for (int o = 16; o > 0; o >>= 1) p += __shfl_xor_sync(0xffffffffu, p, o);
    float s = p * INVSCALE;
    float lr = (s >= 0.f) ? s : NEG * s;
    float hwm = 0.25f * (hw[0] + hw[1] + hw[2] + hw[3]);
    float a = hwm / (1.f + __expf(-lr));
    float v0 = a * g_V2[c2 * 64 + lane];
    float v1 = a * g_V2[c2 * 64 + lane + 32];
    #pragma unroll
    for (int k = 0; k < NSH; k++) {
        int sv = shv[e * NSH + k];
        atomicAdd(&g_x[(size_t)sv * DD + lane],      v0);
        atomicAdd(&g_x[(size_t)sv * DD + lane + 32], v1);
    }
}

// ---------------- pooling + MLP readout --------------------------------------
__global__ void k_pool() {
    int tid = threadIdx.x;
    int col = tid & 63;
    int rg = tid >> 6;   // 0..3
    float sv = 0.f, sc = 0.f;
    for (int r = blockIdx.x * 4 + rg; r < NM; r += gridDim.x * 4) {
        float x = g_x[(size_t)r * DD + col];
        if (r < N_VAR) sv += x; else sc += x;
    }
    atomicAdd(&g_pool[col], sv);
    atomicAdd(&g_pool[64 + col], sc);
}

__global__ void k_mlp(const float* __restrict__ W1, const float* __restrict__ b1,
                      const float* __restrict__ W2, const float* __restrict__ b2,
                      float* __restrict__ out) {
    __shared__ float p[128];
    __shared__ float h[64];
    int tid = threadIdx.x;
    if (tid < 128)
        p[tid] = tanhf(g_pool[tid] * (tid < 64 ? 1.f / N_VAR : 1.f / N_CLA));
    __syncthreads();
    if (tid < 64) {
        float a = b1[tid];
        #pragma unroll 8
        for (int j = 0; j < 128; j++) a = fmaf(p[j], W1[tid * 128 + j], a);
        h[tid] = (a > 0.f) ? a : 0.f;
    }
    __syncthreads();
    if (tid == 0) {
        float s = b2[0];
        for (int i = 0; i < 64; i++) s = fmaf(h[i], W2[i], s);
        out[0] = s;
    }
}

// ---------------- launch ------------------------------------------------------
extern "C" void kernel_launch(void* const* d_in, const int* in_sizes, int n_in,
                              void* d_out, int out_size) {
    (void)in_sizes; (void)n_in; (void)out_size;
    const float* xv   = (const float*)d_in[0];
    const float* xc   = (const float*)d_in[1];
    const float* sat  = (const float*)d_in[2];
    const int*   cvar = (const int*)d_in[3];
    const int*   ccla = (const int*)d_in[4];
    const int*   ei   = (const int*)d_in[5];
    const int*   shv  = (const int*)d_in[6];
    const float* WQ1  = (const float*)d_in[7];
    const float* WK1  = (const float*)d_in[8];
    const float* WV1  = (const float*)d_in[9];
    const float* hw1  = (const float*)d_in[10];
    const float* Wo   = (const float*)d_in[11];
    const float* bo   = (const float*)d_in[12];
    const float* WQ2  = (const float*)d_in[13];
    const float* WK2  = (const float*)d_in[14];
    const float* WV2  = (const float*)d_in[15];
    const float* hw2  = (const float*)d_in[16];
    const float* W1   = (const float*)d_in[17];
    const float* b1   = (const float*)d_in[18];
    const float* W2   = (const float*)d_in[19];
    const float* b2   = (const float*)d_in[20];

    const int projSmem = (3 * 64 * 65 + 8 * 64) * 4;       // 51968
    const int attnSmem = (2 * NN * 65 + 8 * NN + 8 * 64 + NN) * 4 + NN * 4; // 109568
    const int finSmem  = (64 * 65 + 8 * 64) * 4;           // 18688
    cudaFuncSetAttribute(k_proj, cudaFuncAttributeMaxDynamicSharedMemorySize, projSmem);
    cudaFuncSetAttribute(k_attn, cudaFuncAttributeMaxDynamicSharedMemorySize, attnSmem);

    k_init<<<512, 256>>>(xv, xc);
    const int rowBlocks = (NM + 63) / 64;
    for (int it = 0; it < NITER; it++) {
        k_proj<<<rowBlocks, 256, projSmem>>>(WQ1, WK1, WV1);
        k_zero<<<512, 256>>>();
        k_attn<<<NC, 256, attnSmem>>>(cvar, ccla, sat, hw1);
        k_fin<<<rowBlocks, 256, finSmem>>>(Wo, bo);
        k_cf<<<NC, 64>>>(cvar, WQ2, WK2, WV2);
        k_edge<<<(NE + 7) / 8, 256>>>(ei, shv, hw2);
    }
    k_poolzero<<<1, 128>>>();
    k_pool<<<512, 256>>>();
    k_mlp<<<1, 128>>>(W1, b1, W2, b2, (float*)d_out);
}